// round 13
// baseline (speedup 1.0000x reference)
#include <cuda_runtime.h>

#define Vdim   96
#define Kdim   20
#define Bdim   256
#define Ddim   1024
#define NIJ    9
#define GROUPS 144      // 3*3*4*2*2
#define VK     1920     // Vdim*Kdim

// task geometry (proven bodies from R10/R12)
#define BPB     64                  // b's per yphi task
#define SPLITS  (Bdim / BPB)        // 4
#define NPHI    (GROUPS * SPLITS)   // 576 yphi tasks
#define DCHUNK  20                  // d's per Y task
#define NYB     52                  // ceil(1024/20)
#define NTASK_Y (NIJ * NYB)         // 468 Y tasks
#define NTASK   (NTASK_Y + NPHI)    // 1044
#define NPREP   10
#define NBLK    592                 // 148 SMs x 4 resident — one wave
#define T       480
#define NWARP   (T / 32)            // 15

// ---- scratch (static device globals — no runtime allocation) ----
__device__ float        g_ytr[NIJ * Ddim];    // sum over (e,n,c,v) of Y -> [ij][d]
__device__ float        g_L1[NIJ * VK];       // _T0 + log wt_i + log wr_j
__device__ float        g_W2[GROUPS * Kdim];  // lq - logZ + L3 per (group,k)
__device__ float        g_Wb[NIJ * Bdim];     // sum over (enc,v,k) of yphi
__device__ float        g_lmr[4 * Bdim];      // log missing-rate per (sel,b)
__device__ double       g_loss;
__device__ unsigned int g_task;               // work-stealing counter
__device__ unsigned int g_cntY;               // completed Y tasks
__device__ unsigned int g_done;               // blocks drained
__device__ unsigned int g_prep;               // prep blocks completed
// all counters static zero-init; finisher resets them for graph replay

__global__ __launch_bounds__(T, 4) void k_all(
    const float* __restrict__ yphi, const float* __restrict__ Yv,
    const float* __restrict__ T0p,  const float* __restrict__ tp,
    const float* __restrict__ rp,   const float* __restrict__ ep,
    const float* __restrict__ enp,  const float* __restrict__ ecp,
    const int* __restrict__ index,  float* __restrict__ out)
{
    __shared__ float    se[VK], st[VK], sr[VK];            // prep (block 0)
    __shared__ float    sprm[8 * Kdim];
    __shared__ float    scolsum[Kdim], sZraw[NIJ * Kdim], slz[NIJ * Kdim];
    __shared__ float    slpe[4 * Kdim], slpn[2 * Kdim], slpc[2 * Kdim];
    __shared__ float    sW[Kdim];                          // yphi task
    __shared__ float    swb[BPB * 16];                     // [b][warp] pad 16
    __shared__ double   sred[NWARP];
    __shared__ float    sY[T];                             // Y task
    __shared__ double   sfin[256];                         // finisher
    __shared__ unsigned sTask;
    __shared__ int      sFlag, sPrepOk, sLastY;

    int t = threadIdx.x, blk = blockIdx.x;
    int lane = t & 31, w = t >> 5;

    if (t == 0) sPrepOk = 0;

    // ================= PREP (blocks 0..9, before stealing) =================
    if (blk < NPREP) {
        if (blk > 0) {
            // L1 slab for ij = blk-1: _T0 + log wt_i + log wr_j
            int ij = blk - 1;
            int i = ij / 3, j = ij % 3;
            for (int idx = t; idx < VK; idx += T) {
                float t0 = T0p[idx];
                float lwt = 0.f, lwr = 0.f;
                if (i < 2) {
                    float s = 1.f / (1.f + __expf(-tp[idx]));
                    lwt = __logf((i == 0) ? s : 1.f - s);
                }
                if (j < 2) {
                    float s = 1.f / (1.f + __expf(-rp[idx]));
                    lwr = __logf((j == 0) ? s : 1.f - s);
                }
                g_L1[ij * VK + idx] = t0 + lwt + lwr;
            }
        } else {
            // block 0: zeroing + reductions + W2
            if (t < 8 * Kdim)
                sprm[t] = (t < 4 * Kdim) ? ep[t]
                        : (t < 6 * Kdim) ? enp[t - 4 * Kdim]
                                         : ecp[t - 6 * Kdim];
            for (int i = t; i < VK; i += T) {
                se[i] = __expf(T0p[i]);
                st[i] = 1.f / (1.f + __expf(-tp[i]));
                sr[i] = 1.f / (1.f + __expf(-rp[i]));
            }
            for (int i = t; i < NIJ * Bdim; i += T) g_Wb[i] = 0.f;
            if (t == 0) g_loss = 0.0;
            __syncthreads();

            for (int o = w; o < Kdim; o += NWARP) {
                float s = 0.f;
                for (int v = lane; v < Vdim; v += 32) s += se[v * Kdim + o];
#pragma unroll
                for (int off = 16; off; off >>= 1)
                    s += __shfl_down_sync(0xffffffffu, s, off);
                if (lane == 0) scolsum[o] = s;
            }
            for (int o = w; o < NIJ * Kdim; o += NWARP) {
                int ij = o / Kdim, k = o - ij * Kdim, i = ij / 3, j = ij % 3;
                float s = 0.f;
                for (int v = lane; v < Vdim; v += 32) {
                    int r = v * Kdim + k;
                    float wt = (i == 0) ? st[r] : (i == 1) ? 1.f - st[r] : 1.f;
                    float wr = (j == 0) ? sr[r] : (j == 1) ? 1.f - sr[r] : 1.f;
                    s += se[r] * wt * wr;
                }
#pragma unroll
                for (int off = 16; off; off >>= 1)
                    s += __shfl_down_sync(0xffffffffu, s, off);
                if (lane == 0) sZraw[o] = s;
            }
            __syncthreads();

            if (t < Kdim) {
                float s, l;
                s = 0.f; for (int e = 0; e < 4; ++e) s += __expf(sprm[e * Kdim + t]);
                l = __logf(s);
                for (int e = 0; e < 4; ++e) slpe[e * Kdim + t] = sprm[e * Kdim + t] - l;
                s = 0.f; for (int n = 0; n < 2; ++n) s += __expf(sprm[(4 + n) * Kdim + t]);
                l = __logf(s);
                for (int n = 0; n < 2; ++n) slpn[n * Kdim + t] = sprm[(4 + n) * Kdim + t] - l;
                s = 0.f; for (int c = 0; c < 2; ++c) s += __expf(sprm[(6 + c) * Kdim + t]);
                l = __logf(s);
                for (int c = 0; c < 2; ++c) slpc[c * Kdim + t] = sprm[(6 + c) * Kdim + t] - l;
            }
            if (t < NIJ * Kdim) {
                int ij = t / Kdim, k = t - ij * Kdim;
                int i = ij / 3, j = ij % 3;
                float inv = 1.f / scolsum[k];
                float pt = sZraw[2 * Kdim + k] * inv;   // ij=(0,2)
                float pr = sZraw[6 * Kdim + k] * inv;   // ij=(2,0)
                float lqt = (i == 0) ? __logf(pt) : (i == 1) ? __logf(1.f - pt) : 0.f;
                float lqr = (j == 0) ? __logf(pr) : (j == 1) ? __logf(1.f - pr) : 0.f;
                slz[t] = lqt + lqr - __logf(sZraw[t]);
            }
            __syncthreads();

            for (int idx = t; idx < GROUPS * Kdim; idx += T) {
                int g = idx / Kdim, k = idx - g * Kdim;
                int ij = g >> 4, enc = g & 15;
                g_W2[idx] = slz[ij * Kdim + k] + slpe[(enc >> 2) * Kdim + k]
                          + slpn[((enc >> 1) & 1) * Kdim + k]
                          + slpc[(enc & 1) * Kdim + k];
            }
        }
        __syncthreads();
        __threadfence();                       // publish (10 blocks only)
        if (t == 0) atomicAdd(&g_prep, 1u);
    }

    // ================= WORK-STEALING LOOP =================
    for (;;) {
        __syncthreads();                       // protect sTask & smem reuse
        if (t == 0) sTask = atomicAdd(&g_task, 1u);
        __syncthreads();
        unsigned task = sTask;
        if (task >= NTASK) break;

        if (task < NTASK_Y) {
            // ---------------- Y TASK ----------------
            int ij    = task / NYB;
            int chunk = task - ij * NYB;
            int d0 = chunk * DCHUNK;
            int dl = t / 24, vq = t - dl * 24; // 20 d's x 24 float4
            int d  = d0 + dl;
            float s = 0.f;
            if (d < Ddim) {
                const float4* q = (const float4*)Yv
                    + (size_t)ij * (16 * Ddim * 24) + (size_t)d * 24 + vq;
#pragma unroll
                for (int enc = 0; enc < 16; ++enc) {
                    float4 x = q[(size_t)enc * (Ddim * 24)];
                    s += (x.x + x.y) + (x.z + x.w);
                }
            }
            sY[t] = s;
            __syncthreads();
            if (t < DCHUNK && d0 + t < Ddim) {
                float r = 0.f;
#pragma unroll
                for (int v = 0; v < 24; ++v) r += sY[t * 24 + v];
                g_ytr[ij * Ddim + d0 + t] = r;
                __threadfence();               // writer release (20 threads)
            }
            __syncthreads();
            if (t == 0) {
                unsigned v = atomicAdd(&g_cntY, 1u);
                sLastY = (v == NTASK_Y - 1) ? 1 : 0;
            }
            __syncthreads();
            if (sLastY) {
                // all Y done: compute log missing-rates (overlaps yphi tasks)
                if (t < Bdim) {
                    __threadfence();           // acquire
                    int dd = index[t];
                    float y[9];
#pragma unroll
                    for (int ij2 = 0; ij2 < 9; ++ij2) y[ij2] = g_ytr[ij2 * Ddim + dd];
                    float tot = ((y[0] + y[1]) + (y[2] + y[3]))
                              + ((y[4] + y[5]) + (y[6] + y[7])) + y[8];
                    float inv = 1.f / tot;
                    g_lmr[t]            = __logf((y[0] + y[1] + y[3] + y[4]) * inv);
                    g_lmr[Bdim + t]     = __logf((y[2] + y[5]) * inv);
                    g_lmr[2 * Bdim + t] = __logf((y[6] + y[7]) * inv);
                    g_lmr[3 * Bdim + t] = __logf(y[8] * inv);
                    __threadfence();           // release lmr
                }
            }
        } else {
            // ---------------- YPHI TASK (gated on prep, cached) ----------------
            if (!sPrepOk) {
                if (t == 0) {
                    while (atomicAdd(&g_prep, 0u) < NPREP) __nanosleep(64);
                    __threadfence();           // acquire
                    sPrepOk = 1;
                }
                __syncthreads();
            }
            int pblk   = (int)task - NTASK_Y;  // 0..575
            int group  = pblk / SPLITS;        // ij*16 + enc
            int bsplit = pblk - group * SPLITS;
            int ij = group >> 4;

            if (t < Kdim) sW[t] = g_W2[group * Kdim + t];
            __syncthreads();

            float4 wv = *(const float4*)(g_L1 + ij * VK + 4 * t);
            int kb = (4 * t) % Kdim;           // 4|20: never wraps in a float4
            wv.x += sW[kb]; wv.y += sW[kb + 1];
            wv.z += sW[kb + 2]; wv.w += sW[kb + 3];

            const float4* p = (const float4*)(yphi + (size_t)group * (Bdim * VK)
                                                   + (size_t)bsplit * BPB * VK) + t;
            float acc = 0.f;
#pragma unroll 8
            for (int b = 0; b < BPB; ++b) {
                float4 x = p[(size_t)b * (VK / 4)];
                acc += x.x * wv.x; acc += x.y * wv.y;
                acc += x.z * wv.z; acc += x.w * wv.w;
                float s = (x.x + x.y) + (x.z + x.w);
#pragma unroll
                for (int off = 16; off; off >>= 1)
                    s += __shfl_down_sync(0xffffffffu, s, off);
                if (lane == 0) swb[b * 16 + w] = s;
            }
            __syncthreads();
            if (t < BPB) {
                float s = 0.f;
#pragma unroll
                for (int w2 = 0; w2 < NWARP; ++w2) s += swb[t * 16 + w2];
                atomicAdd(&g_Wb[ij * Bdim + bsplit * BPB + t], s);
            }
#pragma unroll
            for (int off = 16; off; off >>= 1)
                acc += __shfl_down_sync(0xffffffffu, acc, off);
            if (lane == 0) sred[w] = (double)acc;
            __syncthreads();
            if (t == 0) {
                double s = 0.0;
#pragma unroll
                for (int w2 = 0; w2 < NWARP; ++w2) s += sred[w2];
                atomicAdd(&g_loss, s);
            }
        }
    }

    // ================= BLOCK DRAIN + FINISHER =================
    if (t < BPB) __threadfence();              // publish this block's Wb/loss
    __syncthreads();
    if (t == 0) sFlag = (atomicAdd(&g_done, 1u) == NBLK - 1) ? 1 : 0;
    __syncthreads();
    if (!sFlag) return;

    if (t < 256) {
        __threadfence();                       // acquire everything
        float wb[9];
#pragma unroll
        for (int ij = 0; ij < 9; ++ij) wb[ij] = g_Wb[ij * Bdim + t];
        float lsel[4] = { g_lmr[t], g_lmr[Bdim + t],
                          g_lmr[2 * Bdim + t], g_lmr[3 * Bdim + t] };
        double acc = 0.0;
#pragma unroll
        for (int ij = 0; ij < 9; ++ij) {
            int i = ij / 3, j = ij % 3;
            int sel = ((i == 2) ? 2 : 0) + ((j == 2) ? 1 : 0);
            acc += (double)wb[ij] * (double)lsel[sel];
        }
        sfin[t] = acc;
    }
    __syncthreads();
    for (int off = 128; off; off >>= 1) {
        if (t < off) sfin[t] += sfin[t + off];
        __syncthreads();
    }
    if (t == 0) {
        double L = atomicAdd(&g_loss, 0.0);    // coherent read
        out[0] = (float)(-(L + sfin[0]) / (double)VK);
        g_task = 0u; g_cntY = 0u; g_done = 0u; g_prep = 0u;  // graph-replay reset
    }
}

// ---------------------------------------------------------------------------
extern "C" void kernel_launch(void* const* d_in, const int* in_sizes, int n_in,
                              void* d_out, int out_size) {
    (void)in_sizes; (void)n_in; (void)out_size;
    const float* yphi = (const float*)d_in[0];
    const float* Yv   = (const float*)d_in[1];
    const float* T0p  = (const float*)d_in[2];
    const float* tp   = (const float*)d_in[3];
    const float* rp   = (const float*)d_in[4];
    const float* ep   = (const float*)d_in[5];
    const float* enp  = (const float*)d_in[6];
    const float* ecp  = (const float*)d_in[7];
    const int*   idx  = (const int*)d_in[8];
    float* out = (float*)d_out;

    k_all<<<NBLK, T>>>(yphi, Yv, T0p, tp, rp, ep, enp, ecp, idx, out);
}

// round 14
// speedup vs baseline: 1.0056x; 1.0056x over previous
#include <cuda_runtime.h>

#define Vdim   96
#define Kdim   20
#define Bdim   256
#define Ddim   1024
#define NIJ    9
#define GROUPS 144      // 3*3*4*2*2
#define VK     1920     // Vdim*Kdim

// kernel 1 geometry: 10 prep blocks + 468 Y blocks (independent, concurrent)
#define DCHUNK 20                  // d's per Y block
#define NYB    52                  // ceil(1024/20)
#define NY     (NIJ * NYB)         // 468
#define NPREP  10
#define NBLK1  (NPREP + NY)        // 478
// kernel 2 geometry: proven fine-grained yphi config
#define BPB    64                  // b's per yphi block
#define SPLITS (Bdim / BPB)        // 4
#define NPHI   (GROUPS * SPLITS)   // 576
#define TMEGA  480
#define NWARP  (TMEGA / 32)        // 15

// ---- scratch (static device globals — no runtime allocation) ----
__device__ float        g_ytr[NIJ * Ddim];    // sum over (e,n,c,v) of Y -> [ij][d]
__device__ float        g_L1[NIJ * VK];       // _T0 + log wt_i + log wr_j per (ij,v,k)
__device__ float        g_W2[GROUPS * Kdim];  // lq - logZ + L3 per (group,k)
__device__ float        g_lmr[4 * Bdim];      // log missing-rate per (sel,b)
__device__ double       g_loss;
__device__ unsigned int g_cntY;               // Y-block completion counter (k1)
__device__ unsigned int g_cnt2;               // yphi-block completion counter (k2)

// ---------------------------------------------------------------------------
// Kernel 1: prep (10 blocks) CONCURRENT with Y reduction (468 blocks).
// Last Y block computes g_lmr. (unchanged from R12 — verified)
// ---------------------------------------------------------------------------
__global__ __launch_bounds__(TMEGA) void k_prepY(
    const float* __restrict__ Yv,  const float* __restrict__ T0p,
    const float* __restrict__ tp,  const float* __restrict__ rp,
    const float* __restrict__ ep,  const float* __restrict__ enp,
    const float* __restrict__ ecp, const int* __restrict__ index)
{
    int blk = blockIdx.x, t = threadIdx.x;
    int lane = t & 31, w = t >> 5;

    if (blk < NPREP) {
        // ================= PREP ROLE =================
        if (blk > 0) {
            int ij = blk - 1;
            int i = ij / 3, j = ij % 3;
            for (int idx = t; idx < VK; idx += TMEGA) {
                float t0 = T0p[idx];
                float lwt = 0.f, lwr = 0.f;
                if (i < 2) {
                    float s = 1.f / (1.f + __expf(-tp[idx]));
                    lwt = __logf((i == 0) ? s : 1.f - s);
                }
                if (j < 2) {
                    float s = 1.f / (1.f + __expf(-rp[idx]));
                    lwr = __logf((j == 0) ? s : 1.f - s);
                }
                g_L1[ij * VK + idx] = t0 + lwt + lwr;
            }
        } else {
            __shared__ float se[VK], st[VK], sr[VK];
            __shared__ float sprm[8 * Kdim];      // ep(4)|enp(2)|ecp(2)
            __shared__ float scolsum[Kdim];
            __shared__ float sZraw[NIJ * Kdim];
            __shared__ float slz[NIJ * Kdim];
            __shared__ float slpe[4 * Kdim], slpn[2 * Kdim], slpc[2 * Kdim];

            if (t < 8 * Kdim)
                sprm[t] = (t < 4 * Kdim) ? ep[t]
                        : (t < 6 * Kdim) ? enp[t - 4 * Kdim]
                                         : ecp[t - 6 * Kdim];
            for (int i = t; i < VK; i += TMEGA) {
                se[i] = __expf(T0p[i]);
                st[i] = 1.f / (1.f + __expf(-tp[i]));
                sr[i] = 1.f / (1.f + __expf(-rp[i]));
            }
            if (t == 0) g_loss = 0.0;
            __syncthreads();

            for (int o = w; o < Kdim; o += NWARP) {
                float s = 0.f;
                for (int v = lane; v < Vdim; v += 32) s += se[v * Kdim + o];
#pragma unroll
                for (int off = 16; off; off >>= 1)
                    s += __shfl_down_sync(0xffffffffu, s, off);
                if (lane == 0) scolsum[o] = s;
            }
            for (int o = w; o < NIJ * Kdim; o += NWARP) {
                int ij = o / Kdim, k = o - ij * Kdim, i = ij / 3, j = ij % 3;
                float s = 0.f;
                for (int v = lane; v < Vdim; v += 32) {
                    int r = v * Kdim + k;
                    float wt = (i == 0) ? st[r] : (i == 1) ? 1.f - st[r] : 1.f;
                    float wr = (j == 0) ? sr[r] : (j == 1) ? 1.f - sr[r] : 1.f;
                    s += se[r] * wt * wr;
                }
#pragma unroll
                for (int off = 16; off; off >>= 1)
                    s += __shfl_down_sync(0xffffffffu, s, off);
                if (lane == 0) sZraw[o] = s;
            }
            __syncthreads();

            if (t < Kdim) {
                float s, l;
                s = 0.f; for (int e = 0; e < 4; ++e) s += __expf(sprm[e * Kdim + t]);
                l = __logf(s);
                for (int e = 0; e < 4; ++e) slpe[e * Kdim + t] = sprm[e * Kdim + t] - l;
                s = 0.f; for (int n = 0; n < 2; ++n) s += __expf(sprm[(4 + n) * Kdim + t]);
                l = __logf(s);
                for (int n = 0; n < 2; ++n) slpn[n * Kdim + t] = sprm[(4 + n) * Kdim + t] - l;
                s = 0.f; for (int c = 0; c < 2; ++c) s += __expf(sprm[(6 + c) * Kdim + t]);
                l = __logf(s);
                for (int c = 0; c < 2; ++c) slpc[c * Kdim + t] = sprm[(6 + c) * Kdim + t] - l;
            }
            if (t < NIJ * Kdim) {
                int ij = t / Kdim, k = t - ij * Kdim;
                int i = ij / 3, j = ij % 3;
                float inv = 1.f / scolsum[k];
                float pt = sZraw[2 * Kdim + k] * inv;   // ij=(0,2)
                float pr = sZraw[6 * Kdim + k] * inv;   // ij=(2,0)
                float lqt = (i == 0) ? __logf(pt) : (i == 1) ? __logf(1.f - pt) : 0.f;
                float lqr = (j == 0) ? __logf(pr) : (j == 1) ? __logf(1.f - pr) : 0.f;
                slz[t] = lqt + lqr - __logf(sZraw[t]);
            }
            __syncthreads();

            for (int idx = t; idx < GROUPS * Kdim; idx += TMEGA) {
                int g = idx / Kdim, k = idx - g * Kdim;
                int ij = g >> 4, enc = g & 15;
                g_W2[idx] = slz[ij * Kdim + k] + slpe[(enc >> 2) * Kdim + k]
                          + slpn[((enc >> 1) & 1) * Kdim + k]
                          + slpc[(enc & 1) * Kdim + k];
            }
        }
        return;   // kernel boundary publishes prep writes
    }

    // ================= Y STREAM ROLE =================
    {
        __shared__ float sY[TMEGA];
        __shared__ int   sLast;
        int yb    = blk - NPREP;
        int ij    = yb / NYB;
        int chunk = yb - ij * NYB;
        int d0 = chunk * DCHUNK;
        int dl = t / 24, vq = t - dl * 24;     // 20 d's x 24 float4
        int d  = d0 + dl;
        float s = 0.f;
        if (d < Ddim) {
            const float4* q = (const float4*)Yv
                + (size_t)ij * (16 * Ddim * 24) + (size_t)d * 24 + vq;
#pragma unroll
            for (int enc = 0; enc < 16; ++enc) {
                float4 x = q[(size_t)enc * (Ddim * 24)];
                s += (x.x + x.y) + (x.z + x.w);
            }
        }
        sY[t] = s;
        __syncthreads();
        if (t < DCHUNK && d0 + t < Ddim) {
            float r = 0.f;
#pragma unroll
            for (int v = 0; v < 24; ++v) r += sY[t * 24 + v];
            g_ytr[ij * Ddim + d0 + t] = r;
            __threadfence();                   // writer release (20 threads)
        }
        __syncthreads();
        if (t == 0) {
            unsigned int v = atomicAdd(&g_cntY, 1u);
            sLast = (v == NY - 1) ? 1 : 0;
        }
        __syncthreads();
        if (!sLast) return;

        if (t == 0) __threadfence();           // acquire
        __syncthreads();
        if (t < Bdim) {
            int dd = index[t];
            float y[9];
#pragma unroll
            for (int ij2 = 0; ij2 < 9; ++ij2) y[ij2] = g_ytr[ij2 * Ddim + dd];
            float tot = ((y[0] + y[1]) + (y[2] + y[3]))
                      + ((y[4] + y[5]) + (y[6] + y[7])) + y[8];
            float inv = 1.f / tot;
            g_lmr[t]            = __logf((y[0] + y[1] + y[3] + y[4]) * inv);  // m00
            g_lmr[Bdim + t]     = __logf((y[2] + y[5]) * inv);                // m01
            g_lmr[2 * Bdim + t] = __logf((y[6] + y[7]) * inv);                // m10
            g_lmr[3 * Bdim + t] = __logf(y[8] * inv);                         // m11
        }
        if (t == 0) g_cntY = 0u;               // reset for next graph replay
    }
}

// ---------------------------------------------------------------------------
// Kernel 2: yphi stream — 2 blocks/SM, 4-way batched loads for MLP.
// ---------------------------------------------------------------------------
__global__ __launch_bounds__(TMEGA, 2) void k_yphi(
    const float* __restrict__ yphi, float* __restrict__ out)
{
    __shared__ float  sW[Kdim];
    __shared__ float  slmr[BPB];
    __shared__ double sred[NWARP];
    __shared__ int    sLast;

    int blk = blockIdx.x, t = threadIdx.x;
    int lane = t & 31, w = t >> 5;

    int group  = blk / SPLITS;                 // ij*16 + enc
    int bsplit = blk - group * SPLITS;
    int ij = group >> 4;
    int i = ij / 3, j = ij % 3;
    int sel = ((i == 2) ? 2 : 0) + ((j == 2) ? 1 : 0);

    if (t < Kdim) sW[t]   = g_W2[group * Kdim + t];
    if (t < BPB)  slmr[t] = g_lmr[sel * Bdim + bsplit * BPB + t];
    __syncthreads();

    // per-thread weights: one load, four smem adds — no MUFU
    float4 wv = *(const float4*)(g_L1 + ij * VK + 4 * t);
    int kb = (4 * t) % Kdim;                   // 4|20: never wraps inside a float4
    wv.x += sW[kb]; wv.y += sW[kb + 1]; wv.z += sW[kb + 2]; wv.w += sW[kb + 3];

    const float4* p = (const float4*)(yphi + (size_t)group * (Bdim * VK)
                                           + (size_t)bsplit * BPB * VK) + t;
    float acc0 = 0.f, acc1 = 0.f, acc2 = 0.f, acc3 = 0.f;
#pragma unroll 4
    for (int b = 0; b < BPB; b += 4) {
        // 4 independent LDG.128 front-batched — high MLP
        float4 x0 = p[(size_t)(b + 0) * (VK / 4)];
        float4 x1 = p[(size_t)(b + 1) * (VK / 4)];
        float4 x2 = p[(size_t)(b + 2) * (VK / 4)];
        float4 x3 = p[(size_t)(b + 3) * (VK / 4)];
        float m0 = slmr[b], m1 = slmr[b + 1], m2 = slmr[b + 2], m3 = slmr[b + 3];
        acc0 += x0.x * wv.x; acc0 += x0.y * wv.y;
        acc0 += x0.z * wv.z; acc0 += x0.w * wv.w;
        acc2 += ((x0.x + x0.y) + (x0.z + x0.w)) * m0;
        acc1 += x1.x * wv.x; acc1 += x1.y * wv.y;
        acc1 += x1.z * wv.z; acc1 += x1.w * wv.w;
        acc3 += ((x1.x + x1.y) + (x1.z + x1.w)) * m1;
        acc0 += x2.x * wv.x; acc0 += x2.y * wv.y;
        acc0 += x2.z * wv.z; acc0 += x2.w * wv.w;
        acc2 += ((x2.x + x2.y) + (x2.z + x2.w)) * m2;
        acc1 += x3.x * wv.x; acc1 += x3.y * wv.y;
        acc1 += x3.z * wv.z; acc1 += x3.w * wv.w;
        acc3 += ((x3.x + x3.y) + (x3.z + x3.w)) * m3;
    }
    float v = (acc0 + acc1) + (acc2 + acc3);
#pragma unroll
    for (int off = 16; off; off >>= 1) v += __shfl_down_sync(0xffffffffu, v, off);
    if (lane == 0) sred[w] = (double)v;
    __syncthreads();
    if (t == 0) {
        double s = 0.0;
#pragma unroll
        for (int w2 = 0; w2 < NWARP; ++w2) s += sred[w2];
        atomicAdd(&g_loss, s);
        __threadfence();                       // order loss-add before counter
        unsigned int c = atomicAdd(&g_cnt2, 1u);
        sLast = (c == NPHI - 1) ? 1 : 0;
    }
    __syncthreads();
    if (!sLast) return;

    if (t == 0) {
        __threadfence();                       // acquire
        double L = atomicAdd(&g_loss, 0.0);    // coherent read
        out[0] = (float)(-L / (double)VK);
        g_cnt2 = 0u;                           // reset for next graph replay
    }
}

// ---------------------------------------------------------------------------
extern "C" void kernel_launch(void* const* d_in, const int* in_sizes, int n_in,
                              void* d_out, int out_size) {
    (void)in_sizes; (void)n_in; (void)out_size;
    const float* yphi = (const float*)d_in[0];
    const float* Yv   = (const float*)d_in[1];
    const float* T0p  = (const float*)d_in[2];
    const float* tp   = (const float*)d_in[3];
    const float* rp   = (const float*)d_in[4];
    const float* ep   = (const float*)d_in[5];
    const float* enp  = (const float*)d_in[6];
    const float* ecp  = (const float*)d_in[7];
    const int*   idx  = (const int*)d_in[8];
    float* out = (float*)d_out;

    k_prepY<<<NBLK1, TMEGA>>>(Yv, T0p, tp, rp, ep, enp, ecp, idx);
    k_yphi<<<NPHI, TMEGA>>>(yphi, out);
}

// round 16
// speedup vs baseline: 1.0584x; 1.0525x over previous
#include <cuda_runtime.h>

#define Vdim   96
#define Kdim   20
#define Bdim   256
#define Ddim   1024
#define NIJ    9
#define GROUPS 144      // 3*3*4*2*2
#define VK     1920     // Vdim*Kdim

// single-kernel geometry: 576 blocks, each = [prep(first 10)] + Y slice + yphi task
#define NPREP   10
#define NBLK    576
#define DSLICE  16                 // d's per Y slice
#define NSLICE  64                 // slices per ij: 64*16 = 1024
#define BPB     64                 // b's per yphi task
#define SPLITS  (Bdim / BPB)       // 4
#define T       480
#define NWARP   (T / 32)           // 15

// ---- scratch (static device globals — no runtime allocation) ----
__device__ float        g_ytr[NIJ * Ddim];    // sum over (e,n,c,v) of Y -> [ij][d]
__device__ float        g_L1[NIJ * VK];       // _T0 + log wt_i + log wr_j
__device__ float        g_W2[GROUPS * Kdim];  // lq - logZ + L3 per (group,k)
__device__ float        g_Wb[NIJ * Bdim];     // sum over (enc,v,k) of yphi
__device__ double       g_loss;
__device__ unsigned int g_prep;               // prep blocks completed
__device__ unsigned int g_cnt2;               // yphi tasks completed
// counters static zero-init; finisher resets them for graph replay

__global__ __launch_bounds__(T, 4) void k_all(
    const float* __restrict__ yphi, const float* __restrict__ Yv,
    const float* __restrict__ T0p,  const float* __restrict__ tp,
    const float* __restrict__ rp,   const float* __restrict__ ep,
    const float* __restrict__ enp,  const float* __restrict__ ecp,
    const int* __restrict__ index,  float* __restrict__ out)
{
    __shared__ float  se[VK], st[VK], sr[VK];              // prep (blk 0)
    __shared__ float  sprm[8 * Kdim];
    __shared__ float  scolsum[Kdim], sZraw[NIJ * Kdim], slz[NIJ * Kdim];
    __shared__ float  slpe[4 * Kdim], slpn[2 * Kdim], slpc[2 * Kdim];
    __shared__ float  sY[384];                             // Y slice
    __shared__ float  sW[Kdim];                            // yphi task
    __shared__ float  swb[BPB * 16];                       // [b][warp] pad 16
    __shared__ double sred[NWARP];
    __shared__ double sfin[256];                           // finisher
    __shared__ int    sLast;

    int blk = blockIdx.x, t = threadIdx.x;
    int lane = t & 31, w = t >> 5;

    // ================= PHASE 1: PREP (blocks 0..9) =================
    if (blk < NPREP) {
        if (blk > 0) {
            // L1 slab for ij = blk-1: _T0 + log wt_i + log wr_j
            int ij = blk - 1;
            int i = ij / 3, j = ij % 3;
            for (int idx = t; idx < VK; idx += T) {
                float t0 = T0p[idx];
                float lwt = 0.f, lwr = 0.f;
                if (i < 2) {
                    float s = 1.f / (1.f + __expf(-tp[idx]));
                    lwt = __logf((i == 0) ? s : 1.f - s);
                }
                if (j < 2) {
                    float s = 1.f / (1.f + __expf(-rp[idx]));
                    lwr = __logf((j == 0) ? s : 1.f - s);
                }
                g_L1[ij * VK + idx] = t0 + lwt + lwr;
            }
        } else {
            // block 0: zeroing + reductions + W2
            if (t < 8 * Kdim)
                sprm[t] = (t < 4 * Kdim) ? ep[t]
                        : (t < 6 * Kdim) ? enp[t - 4 * Kdim]
                                         : ecp[t - 6 * Kdim];
            for (int i = t; i < VK; i += T) {
                se[i] = __expf(T0p[i]);
                st[i] = 1.f / (1.f + __expf(-tp[i]));
                sr[i] = 1.f / (1.f + __expf(-rp[i]));
            }
            for (int i = t; i < NIJ * Bdim; i += T) g_Wb[i] = 0.f;
            if (t == 0) g_loss = 0.0;
            __syncthreads();

            for (int o = w; o < Kdim; o += NWARP) {
                float s = 0.f;
                for (int v = lane; v < Vdim; v += 32) s += se[v * Kdim + o];
#pragma unroll
                for (int off = 16; off; off >>= 1)
                    s += __shfl_down_sync(0xffffffffu, s, off);
                if (lane == 0) scolsum[o] = s;
            }
            for (int o = w; o < NIJ * Kdim; o += NWARP) {
                int ij = o / Kdim, k = o - ij * Kdim, i = ij / 3, j = ij % 3;
                float s = 0.f;
                for (int v = lane; v < Vdim; v += 32) {
                    int r = v * Kdim + k;
                    float wt = (i == 0) ? st[r] : (i == 1) ? 1.f - st[r] : 1.f;
                    float wr = (j == 0) ? sr[r] : (j == 1) ? 1.f - sr[r] : 1.f;
                    s += se[r] * wt * wr;
                }
#pragma unroll
                for (int off = 16; off; off >>= 1)
                    s += __shfl_down_sync(0xffffffffu, s, off);
                if (lane == 0) sZraw[o] = s;
            }
            __syncthreads();

            if (t < Kdim) {
                float s, l;
                s = 0.f; for (int e = 0; e < 4; ++e) s += __expf(sprm[e * Kdim + t]);
                l = __logf(s);
                for (int e = 0; e < 4; ++e) slpe[e * Kdim + t] = sprm[e * Kdim + t] - l;
                s = 0.f; for (int n = 0; n < 2; ++n) s += __expf(sprm[(4 + n) * Kdim + t]);
                l = __logf(s);
                for (int n = 0; n < 2; ++n) slpn[n * Kdim + t] = sprm[(4 + n) * Kdim + t] - l;
                s = 0.f; for (int c = 0; c < 2; ++c) s += __expf(sprm[(6 + c) * Kdim + t]);
                l = __logf(s);
                for (int c = 0; c < 2; ++c) slpc[c * Kdim + t] = sprm[(6 + c) * Kdim + t] - l;
            }
            if (t < NIJ * Kdim) {
                int ij = t / Kdim, k = t - ij * Kdim;
                int i = ij / 3, j = ij % 3;
                float inv = 1.f / scolsum[k];
                float pt = sZraw[2 * Kdim + k] * inv;   // ij=(0,2)
                float pr = sZraw[6 * Kdim + k] * inv;   // ij=(2,0)
                float lqt = (i == 0) ? __logf(pt) : (i == 1) ? __logf(1.f - pt) : 0.f;
                float lqr = (j == 0) ? __logf(pr) : (j == 1) ? __logf(1.f - pr) : 0.f;
                slz[t] = lqt + lqr - __logf(sZraw[t]);
            }
            __syncthreads();

            for (int idx = t; idx < GROUPS * Kdim; idx += T) {
                int g = idx / Kdim, k = idx - g * Kdim;
                int ij = g >> 4, enc = g & 15;
                g_W2[idx] = slz[ij * Kdim + k] + slpe[(enc >> 2) * Kdim + k]
                          + slpn[((enc >> 1) & 1) * Kdim + k]
                          + slpc[(enc & 1) * Kdim + k];
            }
        }
        __syncthreads();
        __threadfence();                       // publish (10 blocks only)
        if (t == 0) atomicAdd(&g_prep, 1u);
        __syncthreads();
    }

    // ================= PHASE 2: Y SLICE (all blocks) =================
    {
        int ijy   = blk / NSLICE;              // 0..8
        int chunk = blk - ijy * NSLICE;        // 0..63
        int d0 = chunk * DSLICE;
        float s = 0.f;
        if (t < 384) {
            int dl = t / 24, vq = t - dl * 24; // 16 d's x 24 float4
            const float4* q = (const float4*)Yv
                + (size_t)ijy * (16 * Ddim * 24) + (size_t)(d0 + dl) * 24 + vq;
#pragma unroll
            for (int enc = 0; enc < 16; ++enc) {
                float4 x = q[(size_t)enc * (Ddim * 24)];
                s += (x.x + x.y) + (x.z + x.w);
            }
            sY[t] = s;
        }
        __syncthreads();
        if (t < DSLICE) {
            float r = 0.f;
#pragma unroll
            for (int v = 0; v < 24; ++v) r += sY[t * 24 + v];
            g_ytr[ijy * Ddim + d0 + t] = r;
            __threadfence();                   // writer release (16 threads)
        }
        __syncthreads();
    }

    // ================= PHASE 3: gate on prep (one-shot, bounded) ==========
    if (t == 0) {
        while (*(volatile unsigned int*)&g_prep < NPREP) __nanosleep(128);
        __threadfence();                       // acquire
    }
    __syncthreads();

    // ================= PHASE 4: YPHI TASK (R8-proven body) =================
    {
        int group  = blk / SPLITS;             // ij*16 + enc
        int bsplit = blk - group * SPLITS;
        int ij = group >> 4;

        if (t < Kdim) sW[t] = g_W2[group * Kdim + t];
        __syncthreads();

        float4 wv = *(const float4*)(g_L1 + ij * VK + 4 * t);
        int kb = (4 * t) % Kdim;               // 4|20: never wraps in a float4
        wv.x += sW[kb]; wv.y += sW[kb + 1]; wv.z += sW[kb + 2]; wv.w += sW[kb + 3];

        const float4* p = (const float4*)(yphi + (size_t)group * (Bdim * VK)
                                               + (size_t)bsplit * BPB * VK) + t;
        float acc = 0.f;
#pragma unroll 8
        for (int b = 0; b < BPB; ++b) {
            float4 x = p[(size_t)b * (VK / 4)];
            acc += x.x * wv.x; acc += x.y * wv.y;
            acc += x.z * wv.z; acc += x.w * wv.w;
            float s = (x.x + x.y) + (x.z + x.w);
#pragma unroll
            for (int off = 16; off; off >>= 1)
                s += __shfl_down_sync(0xffffffffu, s, off);
            if (lane == 0) swb[b * 16 + w] = s;
        }
        __syncthreads();
        if (t < BPB) {
            float s = 0.f;
#pragma unroll
            for (int w2 = 0; w2 < NWARP; ++w2) s += swb[t * 16 + w2];
            atomicAdd(&g_Wb[ij * Bdim + bsplit * BPB + t], s);
            __threadfence();                   // publish Wb (64 threads)
        }
#pragma unroll
        for (int off = 16; off; off >>= 1)
            acc += __shfl_down_sync(0xffffffffu, acc, off);
        if (lane == 0) sred[w] = (double)acc;
        __syncthreads();
        if (t == 0) {
            double s = 0.0;
#pragma unroll
            for (int w2 = 0; w2 < NWARP; ++w2) s += sred[w2];
            atomicAdd(&g_loss, s);
            __threadfence();                   // order loss/Wb before counter
            unsigned int c = atomicAdd(&g_cnt2, 1u);
            sLast = (c == NBLK - 1) ? 1 : 0;
        }
        __syncthreads();
    }
    if (!sLast) return;

    // ================= FINISHER (last block only) =================
    // cnt2==NBLK ⟹ every block finished phase 4 (hence its phase-2 Y writes
    // and its Wb/loss adds are published). Compute lmr + Wb dot + output.
    if (t < 256) {
        __threadfence();                       // acquire
        float wb[9];
#pragma unroll
        for (int ij = 0; ij < 9; ++ij) wb[ij] = g_Wb[ij * Bdim + t];
        int dd = index[t];
        float y[9];
#pragma unroll
        for (int ij = 0; ij < 9; ++ij) y[ij] = g_ytr[ij * Ddim + dd];
        float tot = ((y[0] + y[1]) + (y[2] + y[3]))
                  + ((y[4] + y[5]) + (y[6] + y[7])) + y[8];
        float inv = 1.f / tot;
        float lmr[4];
        lmr[0] = __logf((y[0] + y[1] + y[3] + y[4]) * inv);  // m00
        lmr[1] = __logf((y[2] + y[5]) * inv);                // m01
        lmr[2] = __logf((y[6] + y[7]) * inv);                // m10
        lmr[3] = __logf(y[8] * inv);                         // m11
        double acc = 0.0;
#pragma unroll
        for (int ij = 0; ij < 9; ++ij) {
            int i = ij / 3, j = ij % 3;
            int sel = ((i == 2) ? 2 : 0) + ((j == 2) ? 1 : 0);
            acc += (double)wb[ij] * (double)lmr[sel];
        }
        sfin[t] = acc;
    }
    __syncthreads();
    for (int off = 128; off; off >>= 1) {
        if (t < off) sfin[t] += sfin[t + off];
        __syncthreads();
    }
    if (t == 0) {
        double L = atomicAdd(&g_loss, 0.0);    // coherent read
        out[0] = (float)(-(L + sfin[0]) / (double)VK);
        g_prep = 0u; g_cnt2 = 0u;              // reset for next graph replay
    }
}

// ---------------------------------------------------------------------------
extern "C" void kernel_launch(void* const* d_in, const int* in_sizes, int n_in,
                              void* d_out, int out_size) {
    (void)in_sizes; (void)n_in; (void)out_size;
    const float* yphi = (const float*)d_in[0];
    const float* Yv   = (const float*)d_in[1];
    const float* T0p  = (const float*)d_in[2];
    const float* tp   = (const float*)d_in[3];
    const float* rp   = (const float*)d_in[4];
    const float* ep   = (const float*)d_in[5];
    const float* enp  = (const float*)d_in[6];
    const float* ecp  = (const float*)d_in[7];
    const int*   idx  = (const int*)d_in[8];
    float* out = (float*)d_out;

    k_all<<<NBLK, T>>>(yphi, Yv, T0p, tp, rp, ep, enp, ecp, idx, out);
}

// round 17
// speedup vs baseline: 1.0603x; 1.0018x over previous
#include <cuda_runtime.h>

#define Vdim   96
#define Kdim   20
#define Bdim   256
#define Ddim   1024
#define NIJ    9
#define GROUPS 144      // 3*3*4*2*2
#define VK     1920     // Vdim*Kdim

// Y geometry: 52 chunks of 20 d's per ij; half in k1, half in k2
#define DCHUNK 20
#define NYB    52                  // total chunks per ij
#define NYB1   26                  // chunks per ij in k1
#define NY1    (NIJ * NYB1)        // 234 Y blocks in k1
#define NY2    (NIJ * (NYB - NYB1)) // 234 Y blocks in k2
#define NPREP  10
#define NBLK1  (NPREP + NY1)       // 244
// yphi geometry (R8-proven)
#define BPB    64
#define SPLITS (Bdim / BPB)        // 4
#define NPHI   (GROUPS * SPLITS)   // 576
#define NBLK2  (NY2 + NPHI)        // 810
#define T      480
#define NWARP  (T / 32)            // 15

// ---- scratch (static device globals — no runtime allocation) ----
__device__ float        g_ytr[NIJ * Ddim];    // sum over (e,n,c,v) of Y -> [ij][d]
__device__ float        g_L1[NIJ * VK];       // _T0 + log wt_i + log wr_j
__device__ float        g_W2[GROUPS * Kdim];  // lq - logZ + L3 per (group,k)
__device__ float        g_Wb[NIJ * Bdim];     // sum over (enc,v,k) of yphi
__device__ float        g_lmr[4 * Bdim];      // log missing-rate per (sel,b)
__device__ double       g_loss;
__device__ unsigned int g_cntY;               // Y-part2 completions (k2)
__device__ unsigned int g_done;               // k2 blocks drained
// counters static zero-init; finisher resets them for graph replay

// ---------------------------------------------------------------------------
// Kernel 1: prep (10 blocks) CONCURRENT with Y part-1 (234 blocks).
// Both roles verified (R12); Y role covers d-chunks 0..25 per ij.
// ---------------------------------------------------------------------------
__global__ __launch_bounds__(T) void k_prepY1(
    const float* __restrict__ Yv,  const float* __restrict__ T0p,
    const float* __restrict__ tp,  const float* __restrict__ rp,
    const float* __restrict__ ep,  const float* __restrict__ enp,
    const float* __restrict__ ecp)
{
    int blk = blockIdx.x, t = threadIdx.x;
    int lane = t & 31, w = t >> 5;

    if (blk < NPREP) {
        // ================= PREP ROLE =================
        if (blk > 0) {
            int ij = blk - 1;
            int i = ij / 3, j = ij % 3;
            for (int idx = t; idx < VK; idx += T) {
                float t0 = T0p[idx];
                float lwt = 0.f, lwr = 0.f;
                if (i < 2) {
                    float s = 1.f / (1.f + __expf(-tp[idx]));
                    lwt = __logf((i == 0) ? s : 1.f - s);
                }
                if (j < 2) {
                    float s = 1.f / (1.f + __expf(-rp[idx]));
                    lwr = __logf((j == 0) ? s : 1.f - s);
                }
                g_L1[ij * VK + idx] = t0 + lwt + lwr;
            }
        } else {
            __shared__ float se[VK], st[VK], sr[VK];
            __shared__ float sprm[8 * Kdim];      // ep(4)|enp(2)|ecp(2)
            __shared__ float scolsum[Kdim];
            __shared__ float sZraw[NIJ * Kdim];
            __shared__ float slz[NIJ * Kdim];
            __shared__ float slpe[4 * Kdim], slpn[2 * Kdim], slpc[2 * Kdim];

            if (t < 8 * Kdim)
                sprm[t] = (t < 4 * Kdim) ? ep[t]
                        : (t < 6 * Kdim) ? enp[t - 4 * Kdim]
                                         : ecp[t - 6 * Kdim];
            for (int i = t; i < VK; i += T) {
                se[i] = __expf(T0p[i]);
                st[i] = 1.f / (1.f + __expf(-tp[i]));
                sr[i] = 1.f / (1.f + __expf(-rp[i]));
            }
            for (int i = t; i < NIJ * Bdim; i += T) g_Wb[i] = 0.f;
            if (t == 0) g_loss = 0.0;
            __syncthreads();

            for (int o = w; o < Kdim; o += NWARP) {
                float s = 0.f;
                for (int v = lane; v < Vdim; v += 32) s += se[v * Kdim + o];
#pragma unroll
                for (int off = 16; off; off >>= 1)
                    s += __shfl_down_sync(0xffffffffu, s, off);
                if (lane == 0) scolsum[o] = s;
            }
            for (int o = w; o < NIJ * Kdim; o += NWARP) {
                int ij = o / Kdim, k = o - ij * Kdim, i = ij / 3, j = ij % 3;
                float s = 0.f;
                for (int v = lane; v < Vdim; v += 32) {
                    int r = v * Kdim + k;
                    float wt = (i == 0) ? st[r] : (i == 1) ? 1.f - st[r] : 1.f;
                    float wr = (j == 0) ? sr[r] : (j == 1) ? 1.f - sr[r] : 1.f;
                    s += se[r] * wt * wr;
                }
#pragma unroll
                for (int off = 16; off; off >>= 1)
                    s += __shfl_down_sync(0xffffffffu, s, off);
                if (lane == 0) sZraw[o] = s;
            }
            __syncthreads();

            if (t < Kdim) {
                float s, l;
                s = 0.f; for (int e = 0; e < 4; ++e) s += __expf(sprm[e * Kdim + t]);
                l = __logf(s);
                for (int e = 0; e < 4; ++e) slpe[e * Kdim + t] = sprm[e * Kdim + t] - l;
                s = 0.f; for (int n = 0; n < 2; ++n) s += __expf(sprm[(4 + n) * Kdim + t]);
                l = __logf(s);
                for (int n = 0; n < 2; ++n) slpn[n * Kdim + t] = sprm[(4 + n) * Kdim + t] - l;
                s = 0.f; for (int c = 0; c < 2; ++c) s += __expf(sprm[(6 + c) * Kdim + t]);
                l = __logf(s);
                for (int c = 0; c < 2; ++c) slpc[c * Kdim + t] = sprm[(6 + c) * Kdim + t] - l;
            }
            if (t < NIJ * Kdim) {
                int ij = t / Kdim, k = t - ij * Kdim;
                int i = ij / 3, j = ij % 3;
                float inv = 1.f / scolsum[k];
                float pt = sZraw[2 * Kdim + k] * inv;   // ij=(0,2)
                float pr = sZraw[6 * Kdim + k] * inv;   // ij=(2,0)
                float lqt = (i == 0) ? __logf(pt) : (i == 1) ? __logf(1.f - pt) : 0.f;
                float lqr = (j == 0) ? __logf(pr) : (j == 1) ? __logf(1.f - pr) : 0.f;
                slz[t] = lqt + lqr - __logf(sZraw[t]);
            }
            __syncthreads();

            for (int idx = t; idx < GROUPS * Kdim; idx += T) {
                int g = idx / Kdim, k = idx - g * Kdim;
                int ij = g >> 4, enc = g & 15;
                g_W2[idx] = slz[ij * Kdim + k] + slpe[(enc >> 2) * Kdim + k]
                          + slpn[((enc >> 1) & 1) * Kdim + k]
                          + slpc[(enc & 1) * Kdim + k];
            }
        }
        return;   // kernel boundary publishes prep writes
    }

    // ================= Y PART-1 ROLE (chunks 0..25) =================
    {
        __shared__ float sY[T];
        int yb    = blk - NPREP;
        int ij    = yb / NYB1;
        int chunk = yb - ij * NYB1;            // 0..25
        int d0 = chunk * DCHUNK;
        int dl = t / 24, vq = t - dl * 24;     // 20 d's x 24 float4
        int d  = d0 + dl;
        float s = 0.f;
        {
            const float4* q = (const float4*)Yv
                + (size_t)ij * (16 * Ddim * 24) + (size_t)d * 24 + vq;
#pragma unroll
            for (int enc = 0; enc < 16; ++enc) {
                float4 x = q[(size_t)enc * (Ddim * 24)];
                s += (x.x + x.y) + (x.z + x.w);
            }
        }
        sY[t] = s;
        __syncthreads();
        if (t < DCHUNK) {
            float r = 0.f;
#pragma unroll
            for (int v = 0; v < 24; ++v) r += sY[t * 24 + v];
            g_ytr[ij * Ddim + d0 + t] = r;
        }
        // kernel boundary publishes
    }
}

// ---------------------------------------------------------------------------
// Kernel 2 (MIXED): Y part-2 (234 blocks, first) + yphi (576 blocks).
// Last Y block computes lmr; last overall block runs the finisher.
// ---------------------------------------------------------------------------
__global__ __launch_bounds__(T) void k_main(
    const float* __restrict__ yphi, const float* __restrict__ Yv,
    const int* __restrict__ index,  float* __restrict__ out)
{
    __shared__ double sfin[256];
    __shared__ int    sLast;
    int blk = blockIdx.x, t = threadIdx.x;
    int lane = t & 31, w = t >> 5;

    if (blk < NY2) {
        // ================= Y PART-2 ROLE (chunks 26..51) =================
        __shared__ float sY[T];
        __shared__ int   sLastY;
        int ij    = blk / (NYB - NYB1);
        int chunk = (NYB - NYB1) == 0 ? 0 : (blk - ij * (NYB - NYB1)) + NYB1; // 26..51
        int d0 = chunk * DCHUNK;
        int dl = t / 24, vq = t - dl * 24;     // 20 d's x 24 float4
        int d  = d0 + dl;
        float s = 0.f;
        if (d < Ddim) {
            const float4* q = (const float4*)Yv
                + (size_t)ij * (16 * Ddim * 24) + (size_t)d * 24 + vq;
#pragma unroll
            for (int enc = 0; enc < 16; ++enc) {
                float4 x = q[(size_t)enc * (Ddim * 24)];
                s += (x.x + x.y) + (x.z + x.w);
            }
        }
        sY[t] = s;
        __syncthreads();
        if (t < DCHUNK && d0 + t < Ddim) {
            float r = 0.f;
#pragma unroll
            for (int v = 0; v < 24; ++v) r += sY[t * 24 + v];
            g_ytr[ij * Ddim + d0 + t] = r;
            __threadfence();                   // writer release (20 threads)
        }
        __syncthreads();
        if (t == 0) {
            unsigned int v = atomicAdd(&g_cntY, 1u);
            sLastY = (v == NY2 - 1) ? 1 : 0;
        }
        __syncthreads();
        if (sLastY) {
            // all Y done (part1 via kernel boundary): compute log missing-rates
            if (t < Bdim) {
                __threadfence();               // acquire
                int dd = index[t];
                float y[9];
#pragma unroll
                for (int ij2 = 0; ij2 < 9; ++ij2) y[ij2] = g_ytr[ij2 * Ddim + dd];
                float tot = ((y[0] + y[1]) + (y[2] + y[3]))
                          + ((y[4] + y[5]) + (y[6] + y[7])) + y[8];
                float inv = 1.f / tot;
                g_lmr[t]            = __logf((y[0] + y[1] + y[3] + y[4]) * inv);
                g_lmr[Bdim + t]     = __logf((y[2] + y[5]) * inv);
                g_lmr[2 * Bdim + t] = __logf((y[6] + y[7]) * inv);
                g_lmr[3 * Bdim + t] = __logf(y[8] * inv);
                __threadfence();               // release lmr
            }
            __syncthreads();
        }
    } else {
        // ================= YPHI ROLE (R8-proven body, Wb machinery) ========
        __shared__ float  sW[Kdim];
        __shared__ float  swb[BPB * 16];       // [b][warp] pad 16
        __shared__ double sred[NWARP];

        int pblk   = blk - NY2;                // 0..575
        int group  = pblk / SPLITS;            // ij*16 + enc
        int bsplit = pblk - group * SPLITS;
        int ij = group >> 4;

        if (t < Kdim) sW[t] = g_W2[group * Kdim + t];
        __syncthreads();

        float4 wv = *(const float4*)(g_L1 + ij * VK + 4 * t);
        int kb = (4 * t) % Kdim;               // 4|20: never wraps in a float4
        wv.x += sW[kb]; wv.y += sW[kb + 1]; wv.z += sW[kb + 2]; wv.w += sW[kb + 3];

        const float4* p = (const float4*)(yphi + (size_t)group * (Bdim * VK)
                                               + (size_t)bsplit * BPB * VK) + t;
        float acc = 0.f;
#pragma unroll 8
        for (int b = 0; b < BPB; ++b) {
            float4 x = p[(size_t)b * (VK / 4)];
            acc += x.x * wv.x; acc += x.y * wv.y;
            acc += x.z * wv.z; acc += x.w * wv.w;
            float s = (x.x + x.y) + (x.z + x.w);
#pragma unroll
            for (int off = 16; off; off >>= 1)
                s += __shfl_down_sync(0xffffffffu, s, off);
            if (lane == 0) swb[b * 16 + w] = s;
        }
        __syncthreads();
        if (t < BPB) {
            float s = 0.f;
#pragma unroll
            for (int w2 = 0; w2 < NWARP; ++w2) s += swb[t * 16 + w2];
            atomicAdd(&g_Wb[ij * Bdim + bsplit * BPB + t], s);
            __threadfence();                   // publish Wb (64 threads)
        }
#pragma unroll
        for (int off = 16; off; off >>= 1)
            acc += __shfl_down_sync(0xffffffffu, acc, off);
        if (lane == 0) sred[w] = (double)acc;
        __syncthreads();
        if (t == 0) {
            double s = 0.0;
#pragma unroll
            for (int w2 = 0; w2 < NWARP; ++w2) s += sred[w2];
            atomicAdd(&g_loss, s);
        }
    }

    // ================= COMMON EPILOGUE: drain + finisher =================
    if (t == 0) {
        __threadfence();                       // order this block's work
        unsigned int c = atomicAdd(&g_done, 1u);
        sLast = (c == NBLK2 - 1) ? 1 : 0;
    }
    __syncthreads();
    if (!sLast) return;

    // last block: lmr and all Wb/loss published. Wb·lmr dot + output.
    if (t < 256) {
        __threadfence();                       // acquire
        float wb[9];
#pragma unroll
        for (int ij = 0; ij < 9; ++ij) wb[ij] = g_Wb[ij * Bdim + t];
        float lsel[4] = { g_lmr[t], g_lmr[Bdim + t],
                          g_lmr[2 * Bdim + t], g_lmr[3 * Bdim + t] };
        double acc = 0.0;
#pragma unroll
        for (int ij = 0; ij < 9; ++ij) {
            int i = ij / 3, j = ij % 3;
            int sel = ((i == 2) ? 2 : 0) + ((j == 2) ? 1 : 0);
            acc += (double)wb[ij] * (double)lsel[sel];
        }
        sfin[t] = acc;
    }
    __syncthreads();
    for (int off = 128; off; off >>= 1) {
        if (t < off) sfin[t] += sfin[t + off];
        __syncthreads();
    }
    if (t == 0) {
        double L = atomicAdd(&g_loss, 0.0);    // coherent read
        out[0] = (float)(-(L + sfin[0]) / (double)VK);
        g_cntY = 0u; g_done = 0u;              // reset for next graph replay
    }
}

// ---------------------------------------------------------------------------
extern "C" void kernel_launch(void* const* d_in, const int* in_sizes, int n_in,
                              void* d_out, int out_size) {
    (void)in_sizes; (void)n_in; (void)out_size;
    const float* yphi = (const float*)d_in[0];
    const float* Yv   = (const float*)d_in[1];
    const float* T0p  = (const float*)d_in[2];
    const float* tp   = (const float*)d_in[3];
    const float* rp   = (const float*)d_in[4];
    const float* ep   = (const float*)d_in[5];
    const float* enp  = (const float*)d_in[6];
    const float* ecp  = (const float*)d_in[7];
    const int*   idx  = (const int*)d_in[8];
    float* out = (float*)d_out;

    k_prepY1<<<NBLK1, T>>>(Yv, T0p, tp, rp, ep, enp, ecp);
    k_main<<<NBLK2, T>>>(yphi, Yv, idx, out);
}